// round 11
// baseline (speedup 1.0000x reference)
#include <cuda_runtime.h>
#include <cuda_fp16.h>
#include <math.h>

#define NN 50000
#define NE 800000
#define C1 128
#define C2 64
#define NBLK ((NN + 255) / 256)        // 196 scan blocks
#define E4  (NE / 4)                   // 200000
#define FILL_BLOCKS ((E4 + 255) / 256) // 782

// ---------------- scratch (static device globals — allocation-free) --------
__device__ __half g_h1[(size_t)NN * C1];    // fp16: dinv*(x@W1)
__device__ float  g_agg1[(size_t)NN * C1];  // layer1 output (post relu), fp32
__device__ __half g_h2[(size_t)NN * C2];    // fp16: dinv*(agg1@W2)
__device__ float  g_dinv[NN];
__device__ int    g_cnt[NN];
__device__ int    g_rowstart[NN + 1];
__device__ int    g_rank[NE];               // per-edge rank within its target node
__device__ int    g_src[NE];
__device__ int    g_bsum[NBLK];
__device__ unsigned g_fill_done;            // fill completion counter (join)

// ---------------- tf32 helpers ----------------------------------------------
__device__ __forceinline__ unsigned f2tf32(float f) {
    unsigned r;
    asm("cvt.rna.tf32.f32 %0, %1;" : "=r"(r) : "f"(f));
    return r;
}

__device__ __forceinline__ void mma_tf32(float* d, const unsigned* a, const unsigned* b) {
    asm volatile(
        "mma.sync.aligned.m16n8k8.row.col.f32.tf32.tf32.f32 "
        "{%0,%1,%2,%3}, {%4,%5,%6,%7}, {%8,%9}, {%0,%1,%2,%3};"
        : "+f"(d[0]), "+f"(d[1]), "+f"(d[2]), "+f"(d[3])
        : "r"(a[0]), "r"(a[1]), "r"(a[2]), "r"(a[3]), "r"(b[0]), "r"(b[1]));
}

// release-publish one block's writes (after __syncthreads) / acquire-poll
__device__ __forceinline__ void block_report(unsigned* ctr) {
    asm volatile("red.release.gpu.global.add.u32 [%0], 1;" :: "l"(ctr) : "memory");
}
__device__ __forceinline__ unsigned acquire_load(const unsigned* p) {
    unsigned v;
    asm volatile("ld.acquire.gpu.global.u32 %0, [%1];" : "=r"(v) : "l"(p) : "memory");
    return v;
}

// ---------------- CSR construction ------------------------------------------
// hist also records each edge's arrival rank within its target node.
__global__ void k_hist(const int4* __restrict__ col4, int* cnt, int4* rank4, int e4) {
    cudaGridDependencySynchronize();   // wait memset
    int i = blockIdx.x * blockDim.x + threadIdx.x;
    if (i < e4) {
        int4 c = __ldg(&col4[i]);
        int4 r;
        r.x = atomicAdd(&cnt[c.x], 1);
        r.y = atomicAdd(&cnt[c.y], 1);
        r.z = atomicAdd(&cnt[c.z], 1);
        r.w = atomicAdd(&cnt[c.w], 1);
        rank4[i] = r;
    }
}

__global__ void k_scan_block(const int* __restrict__ cnt, int* ex, int* bsum, int n) {
    cudaGridDependencySynchronize();
    __shared__ int sh[256];
    int i = blockIdx.x * 256 + threadIdx.x;
    int v = (i < n) ? cnt[i] : 0;
    sh[threadIdx.x] = v;
    __syncthreads();
    for (int off = 1; off < 256; off <<= 1) {
        int t = (threadIdx.x >= off) ? sh[threadIdx.x - off] : 0;
        __syncthreads();
        sh[threadIdx.x] += t;
        __syncthreads();
    }
    int inc = sh[threadIdx.x];
    if (i < n) ex[i] = inc - v;
    if (threadIdx.x == 255) bsum[blockIdx.x] = inc;
}

__global__ void k_finalize(int* rowstart, const int* __restrict__ bsum,
                           const int* __restrict__ cnt, float* dinv, int n, int e) {
    cudaGridDependencySynchronize();
    __shared__ int sw[8];
    const int b = blockIdx.x;
    const int t = threadIdx.x;
    const int lane = t & 31;
    int v = (t < b && t < NBLK) ? bsum[t] : 0;
#pragma unroll
    for (int off = 16; off > 0; off >>= 1) v += __shfl_down_sync(0xffffffffu, v, off);
    if (lane == 0) sw[t >> 5] = v;
    __syncthreads();
    if (t < 32) {
        int w = (t < 8) ? sw[t] : 0;
#pragma unroll
        for (int off = 4; off > 0; off >>= 1) w += __shfl_down_sync(0xffffffffu, w, off);
        if (t == 0) sw[0] = w;
    }
    __syncthreads();
    int boff = sw[0];
    int i = b * 256 + t;
    if (i < n) {
        rowstart[i] = rowstart[i] + boff;
        dinv[i]     = rsqrtf((float)cnt[i] + 1.0f);
    }
    if (i == 0) rowstart[n] = e;
}

// fill: atomic-free (uses hist ranks). Triggers early so gemm1 overlaps.
// Publishes completion per block (syncthreads + release-red).
__global__ void k_fill(const int4* __restrict__ rows4, const int4* __restrict__ cols4,
                       const int4* __restrict__ rank4, const int* __restrict__ rowstart,
                       int* src, unsigned* fill_done, int e4) {
    cudaGridDependencySynchronize();             // finalize done (rowstart/dinv)
    cudaTriggerProgrammaticLaunchCompletion();   // release gemm1 now
    int i = blockIdx.x * blockDim.x + threadIdx.x;
    if (i < e4) {
        int4 r = __ldg(&rows4[i]);
        int4 c = __ldg(&cols4[i]);
        int4 k = __ldg(&rank4[i]);
        src[__ldg(&rowstart[c.x]) + k.x] = r.x;
        src[__ldg(&rowstart[c.y]) + k.y] = r.y;
        src[__ldg(&rowstart[c.z]) + k.z] = r.z;
        src[__ldg(&rowstart[c.w]) + k.w] = r.w;
    }
    __syncthreads();
    if (threadIdx.x == 0) block_report(fill_done);
}

// ---------------- tensor-core transform: Hs = fp16(dinv_row * (X @ W)) ------
// TF32 mma m16n8k8. One CTA: 128 rows x full C. 8 warps (4M x 2N).
template <int C, bool SYNC>
__global__ __launch_bounds__(256)
void k_gemm_tc(const float* __restrict__ X, const float* __restrict__ W,
               const float* __restrict__ dinv, __half* __restrict__ Hs, int n) {
    if (SYNC) cudaGridDependencySynchronize();   // layer2: wait gather1
    constexpr int K  = 128;
    constexpr int BM = 128;
    constexpr int XP = 132;
    constexpr int WP = C + 8;
    constexpr int WN = C / 2;
    constexpr int NF = WN / 8;

    extern __shared__ float sm[];
    float* Xs  = sm;              // [BM][XP]
    float* Wsm = sm + BM * XP;    // [K][WP]

    const int tid  = threadIdx.x;
    const int wid  = tid >> 5;
    const int lane = tid & 31;
    const int wm   = wid >> 1;
    const int wn   = wid & 1;
    const int row0 = blockIdx.x * BM;
    const int g    = lane >> 2;
    const int t    = lane & 3;

    for (int i = tid; i < K * (C / 4); i += 256) {
        int r = i / (C / 4), v = i % (C / 4);
        float4 w = __ldg(reinterpret_cast<const float4*>(W + (size_t)r * C) + v);
        float* dst = Wsm + r * WP + v * 4;
        dst[0] = __uint_as_float(f2tf32(w.x));
        dst[1] = __uint_as_float(f2tf32(w.y));
        dst[2] = __uint_as_float(f2tf32(w.z));
        dst[3] = __uint_as_float(f2tf32(w.w));
    }
    for (int i = tid; i < BM * 32; i += 256) {
        int r = i >> 5, v = i & 31;
        float4 xv = make_float4(0.f, 0.f, 0.f, 0.f);
        if (row0 + r < n)
            xv = __ldg(reinterpret_cast<const float4*>(X + (size_t)(row0 + r) * K) + v);
        float* dst = Xs + r * XP + v * 4;
        dst[0] = __uint_as_float(f2tf32(xv.x));
        dst[1] = __uint_as_float(f2tf32(xv.y));
        dst[2] = __uint_as_float(f2tf32(xv.z));
        dst[3] = __uint_as_float(f2tf32(xv.w));
    }
    __syncthreads();

    float acc[2][NF][4];
#pragma unroll
    for (int mi = 0; mi < 2; mi++)
#pragma unroll
        for (int nf = 0; nf < NF; nf++)
#pragma unroll
            for (int q = 0; q < 4; q++) acc[mi][nf][q] = 0.0f;

#pragma unroll
    for (int k0 = 0; k0 < K; k0 += 8) {
        unsigned a[2][4];
#pragma unroll
        for (int mi = 0; mi < 2; mi++) {
            int r = wm * 32 + mi * 16 + g;
            a[mi][0] = __float_as_uint(Xs[r * XP + k0 + t]);
            a[mi][1] = __float_as_uint(Xs[(r + 8) * XP + k0 + t]);
            a[mi][2] = __float_as_uint(Xs[r * XP + k0 + t + 4]);
            a[mi][3] = __float_as_uint(Xs[(r + 8) * XP + k0 + t + 4]);
        }
        unsigned b[NF][2];
#pragma unroll
        for (int nf = 0; nf < NF; nf++) {
            int c = wn * WN + nf * 8 + g;
            b[nf][0] = __float_as_uint(Wsm[(k0 + t) * WP + c]);
            b[nf][1] = __float_as_uint(Wsm[(k0 + t + 4) * WP + c]);
        }
#pragma unroll
        for (int mi = 0; mi < 2; mi++)
#pragma unroll
            for (int nf = 0; nf < NF; nf++)
                mma_tf32(acc[mi][nf], a[mi], b[nf]);
    }

#pragma unroll
    for (int mi = 0; mi < 2; mi++) {
        int rA = row0 + wm * 32 + mi * 16 + g;
        int rB = rA + 8;
        float dA = (rA < n) ? dinv[rA] : 0.f;
        float dB = (rB < n) ? dinv[rB] : 0.f;
#pragma unroll
        for (int nf = 0; nf < NF; nf++) {
            int c = wn * WN + nf * 8 + 2 * t;
            if (rA < n) {
                __half2 hA = __float22half2_rn(
                    make_float2(dA * acc[mi][nf][0], dA * acc[mi][nf][1]));
                *reinterpret_cast<__half2*>(Hs + (size_t)rA * C + c) = hA;
            }
            if (rB < n) {
                __half2 hB = __float22half2_rn(
                    make_float2(dB * acc[mi][nf][2], dB * acc[mi][nf][3]));
                *reinterpret_cast<__half2*>(Hs + (size_t)rB * C + c) = hB;
            }
        }
    }
}

// ---------------- gather layer1 (C=128): 2 warps per node, 64 ch each -------
template <bool RELU>
__global__ void k_gather128(const __half* __restrict__ Hs, const int* __restrict__ rowstart,
                            const int* __restrict__ src, const float* __restrict__ dinv,
                            const float* __restrict__ bias, float* __restrict__ out,
                            const unsigned* __restrict__ fill_done, int n) {
    cudaGridDependencySynchronize();   // gemm1 complete
    // join on fill completion (release/acquire pairing with k_fill)
    if (threadIdx.x == 0) {
        while (acquire_load(fill_done) < (unsigned)FILL_BLOCKS) { }
    }
    __syncthreads();

    int gwarp = (blockIdx.x * blockDim.x + threadIdx.x) >> 5;
    int lane  = threadIdx.x & 31;
    int node  = gwarp >> 1;
    int half  = gwarp & 1;
    if (node >= n) return;
    const int s = rowstart[node];
    const int deg = rowstart[node + 1] - s;
    const int woff = half * 32 + lane;   // word (half2) offset within 64-word row

    unsigned hv = __ldg(reinterpret_cast<const unsigned*>(Hs + (size_t)node * 128) + woff);
    float2 acc = __half22float2(*reinterpret_cast<__half2*>(&hv));

    for (int base = 0; base < deg; base += 32) {
        int m = min(32, deg - base);
        int myidx = (base + lane < deg) ? __ldg(&src[s + base + lane]) : 0;
        for (int k = 0; k < m; k++) {
            int r = __shfl_sync(0xffffffffu, myidx, k);
            unsigned v = __ldg(reinterpret_cast<const unsigned*>(Hs + (size_t)r * 128) + woff);
            float2 q = __half22float2(*reinterpret_cast<__half2*>(&v));
            acc.x += q.x; acc.y += q.y;
        }
    }
    float di = dinv[node];
    float2 bv = __ldg(reinterpret_cast<const float2*>(bias) + woff);
    float2 o = make_float2(fmaf(di, acc.x, bv.x), fmaf(di, acc.y, bv.y));
    if (RELU) { o.x = fmaxf(o.x, 0.f); o.y = fmaxf(o.y, 0.f); }
    reinterpret_cast<float2*>(out)[(size_t)node * 64 + woff] = o;
}

// ---------------- gather layer2 (C=64): warp per node ------------------------
template <bool RELU>
__global__ void k_gather64(const __half* __restrict__ Hs, const int* __restrict__ rowstart,
                           const int* __restrict__ src, const float* __restrict__ dinv,
                           const float* __restrict__ bias, float* __restrict__ out,
                           unsigned* fill_done, int n) {
    cudaGridDependencySynchronize();   // gemm2 complete
    if (blockIdx.x == 0 && threadIdx.x == 0) *fill_done = 0;  // reset for next replay
    int warp = (blockIdx.x * blockDim.x + threadIdx.x) >> 5;
    int lane = threadIdx.x & 31;
    if (warp >= n) return;
    const int node = warp;
    const int s = rowstart[node];
    const int deg = rowstart[node + 1] - s;

    unsigned hv = __ldg(reinterpret_cast<const unsigned*>(Hs + (size_t)node * 64) + lane);
    float2 acc = __half22float2(*reinterpret_cast<__half2*>(&hv));

    for (int base = 0; base < deg; base += 32) {
        int m = min(32, deg - base);
        int myidx = (base + lane < deg) ? __ldg(&src[s + base + lane]) : 0;
        for (int k = 0; k < m; k++) {
            int r = __shfl_sync(0xffffffffu, myidx, k);
            unsigned v = __ldg(reinterpret_cast<const unsigned*>(Hs + (size_t)r * 64) + lane);
            float2 q = __half22float2(*reinterpret_cast<__half2*>(&v));
            acc.x += q.x; acc.y += q.y;
        }
    }
    float di = dinv[node];
    float2 bv = __ldg(reinterpret_cast<const float2*>(bias) + lane);
    float2 o = make_float2(fmaf(di, acc.x, bv.x), fmaf(di, acc.y, bv.y));
    if (RELU) { o.x = fmaxf(o.x, 0.f); o.y = fmaxf(o.y, 0.f); }
    reinterpret_cast<float2*>(out)[(size_t)node * 32 + lane] = o;
}

// ---------------- PDL launch helper ------------------------------------------
template <typename F, typename... Args>
static inline void launch_pdl(F func, int grid, int block, size_t smem, Args... args) {
    cudaLaunchConfig_t cfg = {};
    cfg.gridDim = dim3(grid, 1, 1);
    cfg.blockDim = dim3(block, 1, 1);
    cfg.dynamicSmemBytes = smem;
    cfg.stream = 0;
    cudaLaunchAttribute attr[1];
    attr[0].id = cudaLaunchAttributeProgrammaticStreamSerialization;
    attr[0].val.programmaticStreamSerializationAllowed = 1;
    cfg.attrs = attr;
    cfg.numAttrs = 1;
    cudaLaunchKernelEx(&cfg, func, args...);
}

// ---------------- launch -----------------------------------------------------
extern "C" void kernel_launch(void* const* d_in, const int* in_sizes, int n_in,
                              void* d_out, int out_size) {
    const float* x  = (const float*)d_in[0];
    const int*   ei = (const int*)d_in[1];   // rows = ei, cols = ei + NE
    const float* W1 = (const float*)d_in[2];
    const float* b1 = (const float*)d_in[3];
    const float* W2 = (const float*)d_in[4];
    const float* b2 = (const float*)d_in[5];
    float* out = (float*)d_out;

    const int4* rows4 = (const int4*)ei;
    const int4* cols4 = (const int4*)(ei + NE);

    __half *h1, *h2;
    float *agg1, *dinv;
    int *cnt, *rowstart, *rankA, *srcA, *bsum;
    unsigned* fdone;
    cudaGetSymbolAddress((void**)&h1,       g_h1);
    cudaGetSymbolAddress((void**)&agg1,     g_agg1);
    cudaGetSymbolAddress((void**)&h2,       g_h2);
    cudaGetSymbolAddress((void**)&dinv,     g_dinv);
    cudaGetSymbolAddress((void**)&cnt,      g_cnt);
    cudaGetSymbolAddress((void**)&rowstart, g_rowstart);
    cudaGetSymbolAddress((void**)&rankA,    g_rank);
    cudaGetSymbolAddress((void**)&srcA,     g_src);
    cudaGetSymbolAddress((void**)&bsum,     g_bsum);
    cudaGetSymbolAddress((void**)&fdone,    g_fill_done);

    const int T = 256;
    const int SMEM1 = (128 * 132 + 128 * (C1 + 8)) * (int)sizeof(float);  // 137216
    const int SMEM2 = (128 * 132 + 128 * (C2 + 8)) * (int)sizeof(float);  // 104448
    cudaFuncSetAttribute((const void*)k_gemm_tc<C1, false>,
                         cudaFuncAttributeMaxDynamicSharedMemorySize, SMEM1);
    cudaFuncSetAttribute((const void*)k_gemm_tc<C2, true>,
                         cudaFuncAttributeMaxDynamicSharedMemorySize, SMEM2);

    const int GB  = (NN + 127) / 128;           // gemm blocks (391)
    const int GW1 = (NN * 2 * 32 + T - 1) / T;  // gather1 blocks (2 warps/node)
    const int GW2 = (NN * 32 + T - 1) / T;      // gather2 blocks (warp/node)

    // ---- CSR build (PDL chain; semantics = stream order) ----
    cudaMemsetAsync(cnt, 0, NN * sizeof(int), 0);
    launch_pdl(k_hist, (E4 + T - 1) / T, T, 0, cols4, cnt, (int4*)rankA, E4);
    launch_pdl(k_scan_block, NBLK, 256, 0, (const int*)cnt, rowstart, bsum, NN);
    launch_pdl(k_finalize, NBLK, 256, 0, rowstart, (const int*)bsum,
               (const int*)cnt, dinv, NN, NE);
    // fill triggers early (after its gridsync) -> gemm1 overlaps fill
    launch_pdl(k_fill, FILL_BLOCKS, T, 0, rows4, cols4, (const int4*)rankA,
               (const int*)rowstart, srcA, fdone, E4);

    // ---- layer 1 ----
    launch_pdl(k_gemm_tc<C1, false>, GB, T, SMEM1, x, W1, (const float*)dinv, h1, NN);
    launch_pdl(k_gather128<true>, GW1, T, 0, (const __half*)h1,
               (const int*)rowstart, (const int*)srcA, (const float*)dinv,
               b1, agg1, (const unsigned*)fdone, NN);

    // ---- layer 2 ----
    launch_pdl(k_gemm_tc<C2, true>, GB, T, SMEM2, (const float*)agg1, W2,
               (const float*)dinv, h2, NN);
    launch_pdl(k_gather64<false>, GW2, T, 0, (const __half*)h2,
               (const int*)rowstart, (const int*)srcA, (const float*)dinv,
               b2, out, fdone, NN);
}

// round 12
// speedup vs baseline: 1.1075x; 1.1075x over previous
#include <cuda_runtime.h>
#include <cuda_fp16.h>
#include <math.h>

#define NN 50000
#define NE 800000
#define C1 128
#define C2 64
#define NBLK ((NN + 255) / 256)        // 196 scan blocks
#define E4  (NE / 4)                   // 200000
#define FILL_BLOCKS ((NE + 255) / 256) // 3125

// ---------------- scratch (static device globals — allocation-free) --------
__device__ __half g_h1[(size_t)NN * C1];    // fp16: dinv*(x@W1)
__device__ float  g_agg1[(size_t)NN * C1];  // layer1 output (post relu), fp32
__device__ __half g_h2[(size_t)NN * C2];    // fp16: dinv*(agg1@W2)
__device__ float  g_dinv[NN];
__device__ int    g_cnt[NN];
__device__ int    g_rowstart[NN + 1];
__device__ int    g_cursor[NN];
__device__ int    g_src[NE];
__device__ int    g_bsum[NBLK];
__device__ unsigned g_fill_done;            // fill completion counter (join)

// ---------------- tf32 helpers ----------------------------------------------
__device__ __forceinline__ unsigned f2tf32(float f) {
    unsigned r;
    asm("cvt.rna.tf32.f32 %0, %1;" : "=r"(r) : "f"(f));
    return r;
}

__device__ __forceinline__ void mma_tf32(float* d, const unsigned* a, const unsigned* b) {
    asm volatile(
        "mma.sync.aligned.m16n8k8.row.col.f32.tf32.tf32.f32 "
        "{%0,%1,%2,%3}, {%4,%5,%6,%7}, {%8,%9}, {%0,%1,%2,%3};"
        : "+f"(d[0]), "+f"(d[1]), "+f"(d[2]), "+f"(d[3])
        : "r"(a[0]), "r"(a[1]), "r"(a[2]), "r"(a[3]), "r"(b[0]), "r"(b[1]));
}

// release-publish one block's writes (after __syncthreads) / acquire-poll
__device__ __forceinline__ void block_report(unsigned* ctr) {
    asm volatile("red.release.gpu.global.add.u32 [%0], 1;" :: "l"(ctr) : "memory");
}
__device__ __forceinline__ unsigned acquire_load(const unsigned* p) {
    unsigned v;
    asm volatile("ld.acquire.gpu.global.u32 %0, [%1];" : "=r"(v) : "l"(p) : "memory");
    return v;
}

// ---------------- CSR construction ------------------------------------------
__global__ void k_hist(const int4* __restrict__ col4, int* cnt, int e4) {
    cudaGridDependencySynchronize();   // wait memset
    int i = blockIdx.x * blockDim.x + threadIdx.x;
    if (i < e4) {
        int4 c = __ldg(&col4[i]);
        atomicAdd(&cnt[c.x], 1);
        atomicAdd(&cnt[c.y], 1);
        atomicAdd(&cnt[c.z], 1);
        atomicAdd(&cnt[c.w], 1);
    }
}

__global__ void k_scan_block(const int* __restrict__ cnt, int* ex, int* bsum, int n) {
    cudaGridDependencySynchronize();
    __shared__ int sh[256];
    int i = blockIdx.x * 256 + threadIdx.x;
    int v = (i < n) ? cnt[i] : 0;
    sh[threadIdx.x] = v;
    __syncthreads();
    for (int off = 1; off < 256; off <<= 1) {
        int t = (threadIdx.x >= off) ? sh[threadIdx.x - off] : 0;
        __syncthreads();
        sh[threadIdx.x] += t;
        __syncthreads();
    }
    int inc = sh[threadIdx.x];
    if (i < n) ex[i] = inc - v;
    if (threadIdx.x == 255) bsum[blockIdx.x] = inc;
}

__global__ void k_finalize(int* rowstart, int* cursor, const int* __restrict__ bsum,
                           const int* __restrict__ cnt, float* dinv, int n, int e) {
    cudaGridDependencySynchronize();
    __shared__ int sw[8];
    const int b = blockIdx.x;
    const int t = threadIdx.x;
    const int lane = t & 31;
    int v = (t < b && t < NBLK) ? bsum[t] : 0;
#pragma unroll
    for (int off = 16; off > 0; off >>= 1) v += __shfl_down_sync(0xffffffffu, v, off);
    if (lane == 0) sw[t >> 5] = v;
    __syncthreads();
    if (t < 32) {
        int w = (t < 8) ? sw[t] : 0;
#pragma unroll
        for (int off = 4; off > 0; off >>= 1) w += __shfl_down_sync(0xffffffffu, w, off);
        if (t == 0) sw[0] = w;
    }
    __syncthreads();
    int boff = sw[0];
    int i = b * 256 + t;
    if (i < n) {
        int rs = rowstart[i] + boff;
        rowstart[i] = rs;
        cursor[i]   = rs;
        dinv[i]     = rsqrtf((float)cnt[i] + 1.0f);
    }
    if (i == 0) rowstart[n] = e;
}

// fill: gridsync (finalize done -> cursor/dinv ready), THEN trigger so the
// following PDL gemm1 (reads dinv) overlaps fill's execution. One release-red
// per block publishes this block's scattered src stores (join for gather1).
__global__ void k_fill(const int* __restrict__ rows, const int* __restrict__ cols,
                       int* cursor, int* src, unsigned* fill_done, int e) {
    cudaGridDependencySynchronize();             // finalize done
    cudaTriggerProgrammaticLaunchCompletion();   // release gemm1 now
    int i = blockIdx.x * blockDim.x + threadIdx.x;
    if (i < e) {
        int p = atomicAdd(&cursor[cols[i]], 1);
        src[p] = rows[i];
    }
    __syncthreads();                             // block stores happen-before t0
    if (threadIdx.x == 0) block_report(fill_done);
}

// ---------------- tensor-core transform: Hs = fp16(dinv_row * (X @ W)) ------
// TF32 mma m16n8k8. One CTA: 128 rows x full C. 8 warps (4M x 2N).
template <int C, bool SYNC>
__global__ __launch_bounds__(256)
void k_gemm_tc(const float* __restrict__ X, const float* __restrict__ W,
               const float* __restrict__ dinv, __half* __restrict__ Hs, int n) {
    if (SYNC) cudaGridDependencySynchronize();   // layer2: wait gather1
    constexpr int K  = 128;
    constexpr int BM = 128;
    constexpr int XP = 132;       // X pitch: A-frag banks distinct
    constexpr int WP = C + 8;     // W pitch: B-frag banks distinct
    constexpr int WN = C / 2;
    constexpr int NF = WN / 8;

    extern __shared__ float sm[];
    float* Xs  = sm;              // [BM][XP]
    float* Wsm = sm + BM * XP;    // [K][WP]

    const int tid  = threadIdx.x;
    const int wid  = tid >> 5;
    const int lane = tid & 31;
    const int wm   = wid >> 1;
    const int wn   = wid & 1;
    const int row0 = blockIdx.x * BM;
    const int g    = lane >> 2;
    const int t    = lane & 3;

    for (int i = tid; i < K * (C / 4); i += 256) {
        int r = i / (C / 4), v = i % (C / 4);
        float4 w = __ldg(reinterpret_cast<const float4*>(W + (size_t)r * C) + v);
        float* dst = Wsm + r * WP + v * 4;
        dst[0] = __uint_as_float(f2tf32(w.x));
        dst[1] = __uint_as_float(f2tf32(w.y));
        dst[2] = __uint_as_float(f2tf32(w.z));
        dst[3] = __uint_as_float(f2tf32(w.w));
    }
    for (int i = tid; i < BM * 32; i += 256) {
        int r = i >> 5, v = i & 31;
        float4 xv = make_float4(0.f, 0.f, 0.f, 0.f);
        if (row0 + r < n)
            xv = __ldg(reinterpret_cast<const float4*>(X + (size_t)(row0 + r) * K) + v);
        float* dst = Xs + r * XP + v * 4;
        dst[0] = __uint_as_float(f2tf32(xv.x));
        dst[1] = __uint_as_float(f2tf32(xv.y));
        dst[2] = __uint_as_float(f2tf32(xv.z));
        dst[3] = __uint_as_float(f2tf32(xv.w));
    }
    __syncthreads();

    float acc[2][NF][4];
#pragma unroll
    for (int mi = 0; mi < 2; mi++)
#pragma unroll
        for (int nf = 0; nf < NF; nf++)
#pragma unroll
            for (int q = 0; q < 4; q++) acc[mi][nf][q] = 0.0f;

#pragma unroll
    for (int k0 = 0; k0 < K; k0 += 8) {
        unsigned a[2][4];
#pragma unroll
        for (int mi = 0; mi < 2; mi++) {
            int r = wm * 32 + mi * 16 + g;
            a[mi][0] = __float_as_uint(Xs[r * XP + k0 + t]);
            a[mi][1] = __float_as_uint(Xs[(r + 8) * XP + k0 + t]);
            a[mi][2] = __float_as_uint(Xs[r * XP + k0 + t + 4]);
            a[mi][3] = __float_as_uint(Xs[(r + 8) * XP + k0 + t + 4]);
        }
        unsigned b[NF][2];
#pragma unroll
        for (int nf = 0; nf < NF; nf++) {
            int c = wn * WN + nf * 8 + g;
            b[nf][0] = __float_as_uint(Wsm[(k0 + t) * WP + c]);
            b[nf][1] = __float_as_uint(Wsm[(k0 + t + 4) * WP + c]);
        }
#pragma unroll
        for (int mi = 0; mi < 2; mi++)
#pragma unroll
            for (int nf = 0; nf < NF; nf++)
                mma_tf32(acc[mi][nf], a[mi], b[nf]);
    }

#pragma unroll
    for (int mi = 0; mi < 2; mi++) {
        int rA = row0 + wm * 32 + mi * 16 + g;
        int rB = rA + 8;
        float dA = (rA < n) ? dinv[rA] : 0.f;
        float dB = (rB < n) ? dinv[rB] : 0.f;
#pragma unroll
        for (int nf = 0; nf < NF; nf++) {
            int c = wn * WN + nf * 8 + 2 * t;
            if (rA < n) {
                __half2 hA = __float22half2_rn(
                    make_float2(dA * acc[mi][nf][0], dA * acc[mi][nf][1]));
                *reinterpret_cast<__half2*>(Hs + (size_t)rA * C + c) = hA;
            }
            if (rB < n) {
                __half2 hB = __float22half2_rn(
                    make_float2(dB * acc[mi][nf][2], dB * acc[mi][nf][3]));
                *reinterpret_cast<__half2*>(Hs + (size_t)rB * C + c) = hB;
            }
        }
    }
}

// ---------------- CSR gather (fp16 Hs, shfl-batched indices) ----------------
// WAIT: acquire-join on fill counter (gather1). RESET: zero counter (gather2).
template <int C, bool RELU, bool WAIT, bool RESET>
__global__ void k_gather(const __half* __restrict__ Hs, const int* __restrict__ rowstart,
                         const int* __restrict__ src, const float* __restrict__ dinv,
                         const float* __restrict__ bias, float* __restrict__ out,
                         unsigned* fill_done, int n) {
    cudaGridDependencySynchronize();   // predecessor gemm complete
    if (RESET) {
        if (blockIdx.x == 0 && threadIdx.x == 0) *fill_done = 0;
    }
    if (WAIT) {
        if (threadIdx.x == 0) {
            while (acquire_load(fill_done) < (unsigned)FILL_BLOCKS) { }
        }
        __syncthreads();
    }
    int warp = (blockIdx.x * blockDim.x + threadIdx.x) >> 5;
    int lane = threadIdx.x & 31;
    if (warp >= n) return;
    const int node = warp;
    const int s = rowstart[node];
    const int deg = rowstart[node + 1] - s;

    if (C == 128) {
        uint2 hv = __ldg(reinterpret_cast<const uint2*>(Hs + (size_t)node * 128) + lane);
        float2 p0 = __half22float2(*reinterpret_cast<__half2*>(&hv.x));
        float2 p1 = __half22float2(*reinterpret_cast<__half2*>(&hv.y));
        float4 acc = make_float4(p0.x, p0.y, p1.x, p1.y);

        for (int base = 0; base < deg; base += 32) {
            int m = min(32, deg - base);
            int myidx = (base + lane < deg) ? __ldg(&src[s + base + lane]) : 0;
            for (int k = 0; k < m; k++) {
                int r = __shfl_sync(0xffffffffu, myidx, k);
                uint2 v = __ldg(reinterpret_cast<const uint2*>(Hs + (size_t)r * 128) + lane);
                float2 q0 = __half22float2(*reinterpret_cast<__half2*>(&v.x));
                float2 q1 = __half22float2(*reinterpret_cast<__half2*>(&v.y));
                acc.x += q0.x; acc.y += q0.y; acc.z += q1.x; acc.w += q1.y;
            }
        }
        float di = dinv[node];
        float4 bv = __ldg(reinterpret_cast<const float4*>(bias) + lane);
        float4 o = make_float4(fmaf(di, acc.x, bv.x), fmaf(di, acc.y, bv.y),
                               fmaf(di, acc.z, bv.z), fmaf(di, acc.w, bv.w));
        if (RELU) {
            o.x = fmaxf(o.x, 0.f); o.y = fmaxf(o.y, 0.f);
            o.z = fmaxf(o.z, 0.f); o.w = fmaxf(o.w, 0.f);
        }
        reinterpret_cast<float4*>(out)[(size_t)node * 32 + lane] = o;
    } else {
        unsigned hv = __ldg(reinterpret_cast<const unsigned*>(Hs + (size_t)node * 64) + lane);
        float2 acc = __half22float2(*reinterpret_cast<__half2*>(&hv));

        for (int base = 0; base < deg; base += 32) {
            int m = min(32, deg - base);
            int myidx = (base + lane < deg) ? __ldg(&src[s + base + lane]) : 0;
            for (int k = 0; k < m; k++) {
                int r = __shfl_sync(0xffffffffu, myidx, k);
                unsigned v = __ldg(reinterpret_cast<const unsigned*>(Hs + (size_t)r * 64) + lane);
                float2 q = __half22float2(*reinterpret_cast<__half2*>(&v));
                acc.x += q.x; acc.y += q.y;
            }
        }
        float di = dinv[node];
        float2 bv = __ldg(reinterpret_cast<const float2*>(bias) + lane);
        float2 o = make_float2(fmaf(di, acc.x, bv.x), fmaf(di, acc.y, bv.y));
        if (RELU) { o.x = fmaxf(o.x, 0.f); o.y = fmaxf(o.y, 0.f); }
        reinterpret_cast<float2*>(out)[(size_t)node * 32 + lane] = o;
    }
}

// ---------------- PDL launch helper ------------------------------------------
template <typename F, typename... Args>
static inline void launch_pdl(F func, int grid, int block, size_t smem, Args... args) {
    cudaLaunchConfig_t cfg = {};
    cfg.gridDim = dim3(grid, 1, 1);
    cfg.blockDim = dim3(block, 1, 1);
    cfg.dynamicSmemBytes = smem;
    cfg.stream = 0;
    cudaLaunchAttribute attr[1];
    attr[0].id = cudaLaunchAttributeProgrammaticStreamSerialization;
    attr[0].val.programmaticStreamSerializationAllowed = 1;
    cfg.attrs = attr;
    cfg.numAttrs = 1;
    cudaLaunchKernelEx(&cfg, func, args...);
}

// ---------------- launch -----------------------------------------------------
extern "C" void kernel_launch(void* const* d_in, const int* in_sizes, int n_in,
                              void* d_out, int out_size) {
    const float* x  = (const float*)d_in[0];
    const int*   ei = (const int*)d_in[1];   // rows = ei, cols = ei + NE
    const float* W1 = (const float*)d_in[2];
    const float* b1 = (const float*)d_in[3];
    const float* W2 = (const float*)d_in[4];
    const float* b2 = (const float*)d_in[5];
    float* out = (float*)d_out;

    const int* rows = ei;
    const int* cols = ei + NE;
    const int4* cols4 = (const int4*)(ei + NE);

    __half *h1, *h2;
    float *agg1, *dinv;
    int *cnt, *rowstart, *cursor, *srcA, *bsum;
    unsigned* fdone;
    cudaGetSymbolAddress((void**)&h1,       g_h1);
    cudaGetSymbolAddress((void**)&agg1,     g_agg1);
    cudaGetSymbolAddress((void**)&h2,       g_h2);
    cudaGetSymbolAddress((void**)&dinv,     g_dinv);
    cudaGetSymbolAddress((void**)&cnt,      g_cnt);
    cudaGetSymbolAddress((void**)&rowstart, g_rowstart);
    cudaGetSymbolAddress((void**)&cursor,   g_cursor);
    cudaGetSymbolAddress((void**)&srcA,     g_src);
    cudaGetSymbolAddress((void**)&bsum,     g_bsum);
    cudaGetSymbolAddress((void**)&fdone,    g_fill_done);

    const int T = 256;
    const int SMEM1 = (128 * 132 + 128 * (C1 + 8)) * (int)sizeof(float);  // 137216
    const int SMEM2 = (128 * 132 + 128 * (C2 + 8)) * (int)sizeof(float);  // 104448
    cudaFuncSetAttribute((const void*)k_gemm_tc<C1, false>,
                         cudaFuncAttributeMaxDynamicSharedMemorySize, SMEM1);
    cudaFuncSetAttribute((const void*)k_gemm_tc<C2, true>,
                         cudaFuncAttributeMaxDynamicSharedMemorySize, SMEM2);

    const int GB = (NN + 127) / 128;          // gemm blocks (391)
    const int GW = (NN * 32 + T - 1) / T;     // gather blocks (warp/node)

    // ---- CSR build (PDL chain; semantics = stream order) ----
    cudaMemsetAsync(cnt, 0, NN * sizeof(int), 0);
    launch_pdl(k_hist, (E4 + T - 1) / T, T, 0, cols4, cnt, E4);
    launch_pdl(k_scan_block, NBLK, 256, 0, (const int*)cnt, rowstart, bsum, NN);
    launch_pdl(k_finalize, NBLK, 256, 0, rowstart, cursor, (const int*)bsum,
               (const int*)cnt, dinv, NN, NE);
    // fill gridsyncs then triggers -> gemm1 overlaps fill, dinv guaranteed
    launch_pdl(k_fill, FILL_BLOCKS, T, 0, rows, cols, cursor, srcA, fdone, NE);

    // ---- layer 1 ----
    launch_pdl(k_gemm_tc<C1, false>, GB, T, SMEM1, x, W1, (const float*)dinv, h1, NN);
    launch_pdl(k_gather<C1, true, true, false>, GW, T, 0, (const __half*)h1,
               (const int*)rowstart, (const int*)srcA, (const float*)dinv,
               b1, agg1, fdone, NN);

    // ---- layer 2 ----
    launch_pdl(k_gemm_tc<C2, true>, GB, T, SMEM2, (const float*)agg1, W2,
               (const float*)dinv, h2, NN);
    launch_pdl(k_gather<C2, false, false, true>, GW, T, 0, (const __half*)h2,
               (const int*)rowstart, (const int*)srcA, (const float*)dinv,
               b2, out, fdone, NN);
}